// round 8
// baseline (speedup 1.0000x reference)
#include <cuda_runtime.h>
#include <cuda_fp16.h>
#include <cstdint>
#include <math.h>

#define BATCH   16384
#define EMB     128
#define NCAT    26
#define XDIM    480

typedef __half fp16;

// ---------------- scratch (device globals; allocation-free) ----------------
__device__ fp16  g_h1 [BATCH * 512];
__device__ fp16  g_h2 [BATCH * 256];
__device__ fp16  g_bt [BATCH * 128];
__device__ fp16  g_x  [BATCH * XDIM];
__device__ fp16  g_t1 [BATCH * 1024];
__device__ fp16  g_t2 [BATCH * 1024];
__device__ fp16  g_t3 [BATCH * 512];
__device__ float g_t4 [BATCH * 256];
// converted weights
__device__ fp16  g_w2 [256 * 512];
__device__ fp16  g_w3 [128 * 256];
__device__ fp16  g_u1 [1024 * XDIM];
__device__ fp16  g_u2 [1024 * 1024];
__device__ fp16  g_u3 [512 * 1024];
__device__ fp16  g_u4 [256 * 512];

// ======================= helpers ============================================
__device__ __forceinline__ uint32_t smem_u32(const void* p) {
    uint32_t a;
    asm("{ .reg .u64 t; cvta.to.shared.u64 t, %1; cvt.u32.u64 %0, t; }"
        : "=r"(a) : "l"(p));
    return a;
}

#define LDSM4(r0, r1, r2, r3, addr) \
    asm volatile("ldmatrix.sync.aligned.m8n8.x4.shared.b16 {%0,%1,%2,%3}, [%4];" \
        : "=r"(r0), "=r"(r1), "=r"(r2), "=r"(r3) : "r"(addr))

// fp32-accumulate MMA (used by interact)
#define MMA_F16(c, a, b0, b1) \
    asm volatile("mma.sync.aligned.m16n8k16.row.col.f32.f16.f16.f32 " \
        "{%0,%1,%2,%3}, {%4,%5,%6,%7}, {%8,%9}, {%0,%1,%2,%3};" \
        : "+f"((c)[0]), "+f"((c)[1]), "+f"((c)[2]), "+f"((c)[3]) \
        : "r"((a)[0]), "r"((a)[1]), "r"((a)[2]), "r"((a)[3]), "r"(b0), "r"(b1))

// fp16-accumulate MMA (2x rate on legacy HMMA path)
#define MMA_F16ACC(c, a, b0, b1) \
    asm volatile("mma.sync.aligned.m16n8k16.row.col.f16.f16.f16.f16 " \
        "{%0,%1}, {%2,%3,%4,%5}, {%6,%7}, {%0,%1};" \
        : "+r"((c)[0]), "+r"((c)[1]) \
        : "r"((a)[0]), "r"((a)[1]), "r"((a)[2]), "r"((a)[3]), "r"(b0), "r"(b1))

#define CP16(dst, src) \
    asm volatile("cp.async.cg.shared.global [%0], [%1], 16;" :: "r"(dst), "l"(src))
#define CP_COMMIT() asm volatile("cp.async.commit_group;" ::: "memory")
#define CP_WAIT2()  asm volatile("cp.async.wait_group 2;" ::: "memory")

// ============ tensor-core GEMM ==============================================
// C = relu?(A @ W^T + b). A [M,K], W [N,K] fp16. Out: Cf fp32 or Ch fp16.
// 128x128 CTA tile, 512 threads (16 warps, 4x4 grid of 32x32 warp tiles).
// K-chunk 32, 4-stage cp.async ring. fp16 accumulators flushed to fp32
// every 64 K (and at the last chunk).
// smem per stage (16KB): A 8KB + W 8KB, 8x8-fp16-matrix-contiguous
// (128B mats, mat idx = (row>>3)*4 + koct). bias at 65536. Total 66048.
#define GEMM_SMEM (4 * 16384 + 512)

__global__ __launch_bounds__(512, 1) void gemm_tc(
    const fp16* __restrict__ A, const fp16* __restrict__ W,
    const float* __restrict__ bias,
    float* __restrict__ Cf, fp16* __restrict__ Ch,
    int K, int N, int relu)
{
    extern __shared__ unsigned char smem[];
    const uint32_t sb = smem_u32(smem);
    const int tid    = threadIdx.x;
    const int lane   = tid & 31;
    const int w      = tid >> 5;
    const int warp_m = w >> 2;        // 0..3 (32-row strip)
    const int warp_n = w & 3;         // 0..3 (32-col strip)
    const int row0   = blockIdx.y * 128;
    const int col0   = blockIdx.x * 128;

    float* sbias = (float*)(smem + 65536);
    if (tid < 128) sbias[tid] = bias[col0 + tid];

    const fp16* Ab = A + (size_t)row0 * K;
    const fp16* Wb = W + (size_t)col0 * K;

    // cp.async mapping: thread -> (row = tid>>2, k-seg = tid&3), 16B each
    const int crow = tid >> 2;
    const int cseg = tid & 3;
    const uint32_t soff = (uint32_t)(((crow >> 3) * 4 + cseg) * 128 + (crow & 7) * 16);

    const int nk = K >> 5;

    // prologue: issue stages 0..2
    #pragma unroll
    for (int pc = 0; pc < 3; pc++) {
        if (pc < nk) {
            const uint32_t bufb = sb + (uint32_t)pc * 16384;
            const size_t go = (size_t)crow * K + pc * 32 + cseg * 8;
            CP16(bufb + soff,        Ab + go);
            CP16(bufb + 8192 + soff, Wb + go);
        }
        CP_COMMIT();
    }

    // ldmatrix lane offsets
    const int g  = lane >> 3;
    const int lr = lane & 7;
    const uint32_t laneA = (uint32_t)((g & 1) * 512 + (g >> 1) * 128 + lr * 16);
    const uint32_t laneB = (uint32_t)((g & 1) * 128 + (g >> 1) * 512 + lr * 16);

    float    accf[2][4][4];
    uint32_t acc16[2][4][2];
    #pragma unroll
    for (int i = 0; i < 2; i++)
        #pragma unroll
        for (int j = 0; j < 4; j++) {
            accf[i][j][0] = accf[i][j][1] = accf[i][j][2] = accf[i][j][3] = 0.0f;
            acc16[i][j][0] = acc16[i][j][1] = 0u;
        }

    for (int ck = 0; ck < nk; ck++) {
        CP_WAIT2();            // stage ck complete (2 newer may be in flight)
        __syncthreads();       // all warps done consuming stage ck-1
        const uint32_t bufb = sb + (uint32_t)(ck & 3) * 16384;

        #pragma unroll
        for (int kk = 0; kk < 2; kk++) {
            const uint32_t koff = (uint32_t)(kk * 256);
            uint32_t a[2][4], b[4][2];
            #pragma unroll
            for (int mt = 0; mt < 2; mt++) {
                const uint32_t ta = bufb
                    + (uint32_t)((warp_m * 4 + mt * 2) * 512) + koff + laneA;
                LDSM4(a[mt][0], a[mt][1], a[mt][2], a[mt][3], ta);
            }
            #pragma unroll
            for (int np = 0; np < 2; np++) {
                const uint32_t tb = bufb + 8192
                    + (uint32_t)((warp_n * 4 + np * 2) * 512) + koff + laneB;
                uint32_t r0, r1, r2, r3;
                LDSM4(r0, r1, r2, r3, tb);
                b[np*2][0] = r0;   b[np*2][1] = r1;
                b[np*2+1][0] = r2; b[np*2+1][1] = r3;
            }
            #pragma unroll
            for (int mt = 0; mt < 2; mt++)
                #pragma unroll
                for (int nt = 0; nt < 4; nt++)
                    MMA_F16ACC(acc16[mt][nt], a[mt], b[nt][0], b[nt][1]);
        }

        // flush fp16 accumulators into fp32 every 64 K and at the end
        if ((ck & 1) || ck == nk - 1) {
            #pragma unroll
            for (int mt = 0; mt < 2; mt++)
                #pragma unroll
                for (int nt = 0; nt < 4; nt++) {
                    float2 lo = __half22float2(*(__half2*)&acc16[mt][nt][0]);
                    float2 hi = __half22float2(*(__half2*)&acc16[mt][nt][1]);
                    accf[mt][nt][0] += lo.x;
                    accf[mt][nt][1] += lo.y;
                    accf[mt][nt][2] += hi.x;
                    accf[mt][nt][3] += hi.y;
                    acc16[mt][nt][0] = 0u;
                    acc16[mt][nt][1] = 0u;
                }
        }

        // issue stage ck+3 into buffer (ck+3)&3 (consumed at iteration ck-1)
        if (ck + 3 < nk) {
            const uint32_t bufb2 = sb + (uint32_t)((ck + 3) & 3) * 16384;
            const size_t go = (size_t)crow * K + (ck + 3) * 32 + cseg * 8;
            CP16(bufb2 + soff,        Ab + go);
            CP16(bufb2 + 8192 + soff, Wb + go);
        }
        CP_COMMIT();   // unconditional: keeps group accounting exact
    }

    // ---- epilogue: bias + relu, fp32 or fp16 stores ----
    const int q  = lane >> 2;
    const int tq = lane & 3;
    #pragma unroll
    for (int mt = 0; mt < 2; mt++) {
        const int r0g = row0 + warp_m * 32 + mt * 16 + q;
        #pragma unroll
        for (int nt = 0; nt < 4; nt++) {
            const int cl = warp_n * 32 + nt * 8 + tq * 2;
            const float bx = sbias[cl], by = sbias[cl + 1];
            float v0 = accf[mt][nt][0] + bx, v1 = accf[mt][nt][1] + by;
            float v2 = accf[mt][nt][2] + bx, v3 = accf[mt][nt][3] + by;
            if (relu) {
                v0 = fmaxf(v0, 0.0f); v1 = fmaxf(v1, 0.0f);
                v2 = fmaxf(v2, 0.0f); v3 = fmaxf(v3, 0.0f);
            }
            const size_t o0 = (size_t)r0g * N + col0 + cl;
            const size_t o1 = (size_t)(r0g + 8) * N + col0 + cl;
            if (Cf) {
                *(float2*)(Cf + o0) = make_float2(v0, v1);
                *(float2*)(Cf + o1) = make_float2(v2, v3);
            }
            if (Ch) {
                *(__half2*)(Ch + o0) = __floats2half2_rn(v0, v1);
                *(__half2*)(Ch + o1) = __floats2half2_rn(v2, v3);
            }
        }
    }
}

// -------- merged prep (fp32->fp16 weights) + bottom layer 1 ----------------
#define N_W2 (256 * 512)
#define N_W3 (128 * 256)
#define N_U1 (1024 * XDIM)
#define N_U2 (1024 * 1024)
#define N_U3 (512 * 1024)
#define N_U4 (256 * 512)
#define N_PREP (N_W2 + N_W3 + N_U1 + N_U2 + N_U3 + N_U4)
#define PREP_BLOCKS ((N_PREP + 255) / 256)

__global__ __launch_bounds__(256) void prep_bottom1_kernel(
    const float* __restrict__ bw2, const float* __restrict__ bw3,
    const float* __restrict__ tw1, const float* __restrict__ tw2,
    const float* __restrict__ tw3, const float* __restrict__ tw4,
    const float* __restrict__ X,   const float* __restrict__ W1,
    const float* __restrict__ b1)
{
    if (blockIdx.x < PREP_BLOCKS) {
        int i = blockIdx.x * 256 + threadIdx.x;
        if (i >= N_PREP) return;
        if (i < N_W2) { g_w2[i] = __float2half(bw2[i]); return; }
        i -= N_W2;
        if (i < N_W3) { g_w3[i] = __float2half(bw3[i]); return; }
        i -= N_W3;
        if (i < N_U1) { g_u1[i] = __float2half(tw1[i]); return; }
        i -= N_U1;
        if (i < N_U2) { g_u2[i] = __float2half(tw2[i]); return; }
        i -= N_U2;
        if (i < N_U3) { g_u3[i] = __float2half(tw3[i]); return; }
        i -= N_U3;
        g_u4[i] = __float2half(tw4[i]);
        return;
    }

    // bottom layer 1: [B,13] -> [B,512] fp16, relu
    __shared__ float ws[512 * 13];
    __shared__ float bs[512];
    __shared__ float xs[32 * 13];
    const int tid  = threadIdx.x;
    const int row0 = (blockIdx.x - PREP_BLOCKS) * 32;

    for (int i = tid; i < 512 * 13; i += 256) ws[i] = W1[i];
    for (int i = tid; i < 512;      i += 256) bs[i] = b1[i];
    for (int i = tid; i < 32 * 13;  i += 256) xs[i] = X[row0 * 13 + i];
    __syncthreads();

    for (int o = tid; o < 32 * 512; o += 256) {
        const int col = o & 511;
        const int row = o >> 9;
        float acc = bs[col];
        #pragma unroll
        for (int k = 0; k < 13; k++)
            acc = fmaf(xs[row * 13 + k], ws[col * 13 + k], acc);
        g_h1[(size_t)(row0 + row) * 512 + col] = __float2half(fmaxf(acc, 0.0f));
    }
}

// ---------------- gather + pairwise interactions (HMMA Gram) ---------------
__global__ __launch_bounds__(128) void interact_kernel(
    const int* __restrict__ cat, const float* __restrict__ emb)
{
    __shared__ __align__(16) unsigned char ism[4 * 8192];
    const int warp = threadIdx.x >> 5;
    const int lane = threadIdx.x & 31;
    const int b    = blockIdx.x * 4 + warp;
    unsigned char* F = ism + warp * 8192;
    const uint32_t fb = smem_u32(F);

    int idxs[NCAT];
    #pragma unroll
    for (int t = 0; t < NCAT; t++) idxs[t] = cat[t * BATCH + b];

    const int c0   = lane * 4;
    const int matc = c0 >> 3;
    const int innc = (c0 & 7) * 2;

    uint2 bv = ((const uint2*)(g_bt + (size_t)b * EMB))[lane];
    {
        const int mat = matc;
        *(uint2*)(F + mat * 128 + (innc ^ ((mat & 7) << 4))) = bv;
    }
    #pragma unroll
    for (int t = 0; t < NCAT; t++) {
        const int r = t + 1;
        float4 e = ((const float4*)(emb + ((size_t)t * 100000 + idxs[t]) * EMB))[lane];
        uint2 p;
        *(__half2*)&p.x = __floats2half2_rn(e.x, e.y);
        *(__half2*)&p.y = __floats2half2_rn(e.z, e.w);
        const int mat = ((r >> 3) << 4) + matc;
        *(uint2*)(F + mat * 128 + ((((r & 7) << 4) + innc) ^ ((mat & 7) << 4))) = p;
    }
    #pragma unroll
    for (int r = 27; r < 32; r++) {
        const int mat = ((r >> 3) << 4) + matc;
        *(uint2*)(F + mat * 128 + ((((r & 7) << 4) + innc) ^ ((mat & 7) << 4))) =
            make_uint2(0u, 0u);
    }
    __syncwarp();

    fp16* xrow = g_x + (size_t)b * XDIM;
    ((uint2*)xrow)[lane] = bv;
    if (lane == 0) xrow[479] = __float2half(0.0f);

    const int g2 = lane >> 3;
    const int lr = lane & 7;

    float acc[2][4][4];
    #pragma unroll
    for (int i = 0; i < 2; i++)
        #pragma unroll
        for (int j = 0; j < 4; j++)
            #pragma unroll
            for (int e = 0; e < 4; e++) acc[i][j][e] = 0.0f;

    #pragma unroll
    for (int k = 0; k < 8; k++) {
        uint32_t a[2][4], bb[4][2];
        #pragma unroll
        for (int mt = 0; mt < 2; mt++) {
            const int mA = ((mt * 2 + (g2 & 1)) << 4) + (k * 2 + (g2 >> 1));
            const uint32_t ad = fb + (uint32_t)(mA * 128)
                              + (uint32_t)((lr * 16) ^ ((mA & 7) << 4));
            LDSM4(a[mt][0], a[mt][1], a[mt][2], a[mt][3], ad);
        }
        #pragma unroll
        for (int np = 0; np < 2; np++) {
            const int mB = ((np * 2 + (g2 >> 1)) << 4) + (k * 2 + (g2 & 1));
            const uint32_t bd = fb + (uint32_t)(mB * 128)
                              + (uint32_t)((lr * 16) ^ ((mB & 7) << 4));
            uint32_t r0, r1, r2, r3;
            LDSM4(r0, r1, r2, r3, bd);
            bb[np*2][0] = r0;   bb[np*2][1] = r1;
            bb[np*2+1][0] = r2; bb[np*2+1][1] = r3;
        }
        #pragma unroll
        for (int mt = 0; mt < 2; mt++)
            #pragma unroll
            for (int nt = 0; nt < 4; nt++)
                MMA_F16(acc[mt][nt], a[mt], bb[nt][0], bb[nt][1]);
    }

    const int q  = lane >> 2;
    const int tq = lane & 3;
    #pragma unroll
    for (int mt = 0; mt < 2; mt++) {
        #pragma unroll
        for (int nt = 0; nt < 4; nt++) {
            const int r1 = mt * 16 + q;
            const int r2 = r1 + 8;
            const int cA = nt * 8 + tq * 2;
            const int cB = cA + 1;
            if (r1 < 27) {
                if (cA < r1) xrow[EMB + r1 * (r1 - 1) / 2 + cA] = __float2half(acc[mt][nt][0]);
                if (cB < r1) xrow[EMB + r1 * (r1 - 1) / 2 + cB] = __float2half(acc[mt][nt][1]);
            }
            if (r2 < 27) {
                if (cA < r2) xrow[EMB + r2 * (r2 - 1) / 2 + cA] = __float2half(acc[mt][nt][2]);
                if (cB < r2) xrow[EMB + r2 * (r2 - 1) / 2 + cB] = __float2half(acc[mt][nt][3]);
            }
        }
    }
}

// ---------------- final layer: dot(256) + sigmoid ---------------------------
__global__ __launch_bounds__(256) void final_kernel(
    const float* __restrict__ w5, const float* __restrict__ b5,
    float* __restrict__ out)
{
    const int warp = threadIdx.x >> 5;
    const int lane = threadIdx.x & 31;
    const int b = blockIdx.x * 8 + warp;
    const float* row = g_t4 + (size_t)b * 256;
    float s = 0.0f;
    #pragma unroll
    for (int j = lane; j < 256; j += 32) s = fmaf(row[j], w5[j], s);
    #pragma unroll
    for (int o = 16; o; o >>= 1) s += __shfl_xor_sync(0xffffffffu, s, o);
    if (lane == 0) out[b] = 1.0f / (1.0f + expf(-(s + b5[0])));
}

// ---------------- launcher --------------------------------------------------
template <typename T>
static T* sym_addr(const void* symbol)
{
    void* p = nullptr;
    cudaGetSymbolAddress(&p, symbol);
    return (T*)p;
}

extern "C" void kernel_launch(void* const* d_in, const int* in_sizes, int n_in,
                              void* d_out, int out_size)
{
    const float* Xnum = (const float*)d_in[0];
    const int*   cat  = (const int*)  d_in[1];
    const float* emb  = (const float*)d_in[2];
    const float* bw1  = (const float*)d_in[3];
    const float* bb1  = (const float*)d_in[4];
    const float* bw2  = (const float*)d_in[5];
    const float* bb2  = (const float*)d_in[6];
    const float* bw3  = (const float*)d_in[7];
    const float* bb3  = (const float*)d_in[8];
    const float* tw1  = (const float*)d_in[9];
    const float* tb1  = (const float*)d_in[10];
    const float* tw2  = (const float*)d_in[11];
    const float* tb2  = (const float*)d_in[12];
    const float* tw3  = (const float*)d_in[13];
    const float* tb3  = (const float*)d_in[14];
    const float* tw4  = (const float*)d_in[15];
    const float* tb4  = (const float*)d_in[16];
    const float* tw5  = (const float*)d_in[17];
    const float* tb5  = (const float*)d_in[18];
    float* out = (float*)d_out;

    fp16* h1 = sym_addr<fp16>(g_h1);
    fp16* h2 = sym_addr<fp16>(g_h2);
    fp16* bt = sym_addr<fp16>(g_bt);
    fp16* x  = sym_addr<fp16>(g_x);
    fp16* t1 = sym_addr<fp16>(g_t1);
    fp16* t2 = sym_addr<fp16>(g_t2);
    fp16* t3 = sym_addr<fp16>(g_t3);
    float* t4 = sym_addr<float>(g_t4);
    fp16* w2 = sym_addr<fp16>(g_w2);
    fp16* w3 = sym_addr<fp16>(g_w3);
    fp16* u1 = sym_addr<fp16>(g_u1);
    fp16* u2 = sym_addr<fp16>(g_u2);
    fp16* u3 = sym_addr<fp16>(g_u3);
    fp16* u4 = sym_addr<fp16>(g_u4);

    cudaFuncSetAttribute(gemm_tc,
                         cudaFuncAttributeMaxDynamicSharedMemorySize, GEMM_SMEM);

    // merged weight prep + bottom layer 1 (1 launch)
    prep_bottom1_kernel<<<PREP_BLOCKS + BATCH / 32, 256>>>(
        bw2, bw3, tw1, tw2, tw3, tw4, Xnum, bw1, bb1);

    // bottom MLP
    gemm_tc<<<dim3(2, BATCH / 128), 512, GEMM_SMEM>>>(
        h1, w2, bb2, nullptr, h2, 512, 256, 1);
    gemm_tc<<<dim3(1, BATCH / 128), 512, GEMM_SMEM>>>(
        h2, w3, bb3, nullptr, bt, 256, 128, 1);

    // gather + interactions -> x [B, 480] fp16
    interact_kernel<<<BATCH / 4, 128>>>(cat, emb);

    // top MLP
    gemm_tc<<<dim3(8, BATCH / 128), 512, GEMM_SMEM>>>(
        x,  u1, tb1, nullptr, t1, XDIM, 1024, 1);
    gemm_tc<<<dim3(8, BATCH / 128), 512, GEMM_SMEM>>>(
        t1, u2, tb2, nullptr, t2, 1024, 1024, 1);
    gemm_tc<<<dim3(4, BATCH / 128), 512, GEMM_SMEM>>>(
        t2, u3, tb3, nullptr, t3, 1024, 512, 1);
    gemm_tc<<<dim3(2, BATCH / 128), 512, GEMM_SMEM>>>(
        t3, u4, tb4, t4, nullptr, 512, 256, 1);

    // final dot + sigmoid
    final_kernel<<<BATCH / 8, 256>>>(tw5, tb5, out);
}

// round 9
// speedup vs baseline: 1.1704x; 1.1704x over previous
#include <cuda_runtime.h>
#include <cuda_fp16.h>
#include <cstdint>
#include <math.h>

#define BATCH   16384
#define EMB     128
#define NCAT    26
#define XDIM    480

typedef __half fp16;

// ---------------- scratch (device globals; allocation-free) ----------------
__device__ fp16  g_h1 [BATCH * 512];
__device__ fp16  g_h2 [BATCH * 256];
__device__ fp16  g_bt [BATCH * 128];
__device__ fp16  g_x  [BATCH * XDIM];
__device__ fp16  g_t1 [BATCH * 1024];
__device__ fp16  g_t2 [BATCH * 1024];
__device__ fp16  g_t3 [BATCH * 512];
__device__ float g_d2 [BATCH * 2];      // per-half-col dot partials
// converted weights
__device__ fp16  g_w2 [256 * 512];
__device__ fp16  g_w3 [128 * 256];
__device__ fp16  g_u1 [1024 * XDIM];
__device__ fp16  g_u2 [1024 * 1024];
__device__ fp16  g_u3 [512 * 1024];
__device__ fp16  g_u4 [256 * 512];

// ======================= helpers ============================================
__device__ __forceinline__ uint32_t smem_u32(const void* p) {
    uint32_t a;
    asm("{ .reg .u64 t; cvta.to.shared.u64 t, %1; cvt.u32.u64 %0, t; }"
        : "=r"(a) : "l"(p));
    return a;
}

#define LDSM4(r0, r1, r2, r3, addr) \
    asm volatile("ldmatrix.sync.aligned.m8n8.x4.shared.b16 {%0,%1,%2,%3}, [%4];" \
        : "=r"(r0), "=r"(r1), "=r"(r2), "=r"(r3) : "r"(addr))

#define MMA_F16(c, a, b0, b1) \
    asm volatile("mma.sync.aligned.m16n8k16.row.col.f32.f16.f16.f32 " \
        "{%0,%1,%2,%3}, {%4,%5,%6,%7}, {%8,%9}, {%0,%1,%2,%3};" \
        : "+f"((c)[0]), "+f"((c)[1]), "+f"((c)[2]), "+f"((c)[3]) \
        : "r"((a)[0]), "r"((a)[1]), "r"((a)[2]), "r"((a)[3]), "r"(b0), "r"(b1))

#define CP16(dst, src) \
    asm volatile("cp.async.cg.shared.global [%0], [%1], 16;" :: "r"(dst), "l"(src))
#define CP_COMMIT() asm volatile("cp.async.commit_group;" ::: "memory")
#define CP_WAIT2()  asm volatile("cp.async.wait_group 2;" ::: "memory")

// ======== shared GEMM mainloop (R7-proven config) ===========================
// 128x128 CTA tile, 256 threads (8 warps, 2x4 of 64x32 warp tiles),
// K-chunk 32, 4-stage cp.async ring, fp32 accumulators.
// smem per stage (16KB): A 8KB + W 8KB, 8x8-fp16-matrix-contiguous
// (128B mats, mat idx = (row>>3)*4 + koct).
#define GEMM_SMEM  (4 * 16384 + 512)
#define DOT_SMEM   (4 * 16384 + 512 + 512 + 2048)

#define GEMM_MAINLOOP(ACC)                                                    \
    const int crow  = tid >> 1;                                               \
    const int cseg0 = (tid & 1) * 2;                                          \
    const uint32_t soffA = (uint32_t)(((crow >> 3) * 4) * 128 + (crow & 7) * 16); \
    const int nk = K >> 5;                                                    \
    _Pragma("unroll")                                                         \
    for (int pc = 0; pc < 3; pc++) {                                          \
        if (pc < nk) {                                                        \
            const uint32_t bufb = sb + (uint32_t)pc * 16384;                  \
            _Pragma("unroll")                                                 \
            for (int s = 0; s < 2; s++) {                                     \
                const int seg = cseg0 + s;                                    \
                const uint32_t so = bufb + soffA + (uint32_t)seg * 128;       \
                const size_t  go = (size_t)crow * K + pc * 32 + seg * 8;      \
                CP16(so,        Ab + go);                                     \
                CP16(so + 8192, Wb + go);                                     \
            }                                                                 \
        }                                                                     \
        CP_COMMIT();                                                          \
    }                                                                         \
    const int g  = lane >> 3;                                                 \
    const int lr = lane & 7;                                                  \
    const uint32_t laneA = (uint32_t)((g & 1) * 512 + (g >> 1) * 128 + lr * 16); \
    const uint32_t laneB = (uint32_t)((g & 1) * 128 + (g >> 1) * 512 + lr * 16); \
    for (int ck = 0; ck < nk; ck++) {                                         \
        CP_WAIT2();                                                           \
        __syncthreads();                                                      \
        const uint32_t bufb = sb + (uint32_t)(ck & 3) * 16384;                \
        _Pragma("unroll")                                                     \
        for (int kk = 0; kk < 2; kk++) {                                      \
            const uint32_t koff = (uint32_t)(kk * 256);                       \
            uint32_t ah[4][4], bh[4][2];                                      \
            _Pragma("unroll")                                                 \
            for (int mt = 0; mt < 4; mt++) {                                  \
                const uint32_t ta = bufb                                      \
                    + (uint32_t)((warp_m * 8 + mt * 2) * 512) + koff + laneA; \
                LDSM4(ah[mt][0], ah[mt][1], ah[mt][2], ah[mt][3], ta);        \
            }                                                                 \
            _Pragma("unroll")                                                 \
            for (int np = 0; np < 2; np++) {                                  \
                const uint32_t tb = bufb + 8192                               \
                    + (uint32_t)((warp_n * 4 + np * 2) * 512) + koff + laneB; \
                uint32_t r0, r1, r2, r3;                                      \
                LDSM4(r0, r1, r2, r3, tb);                                    \
                bh[np*2][0] = r0;   bh[np*2][1] = r1;                         \
                bh[np*2+1][0] = r2; bh[np*2+1][1] = r3;                       \
            }                                                                 \
            _Pragma("unroll")                                                 \
            for (int mt = 0; mt < 4; mt++)                                    \
                _Pragma("unroll")                                             \
                for (int nt = 0; nt < 4; nt++)                                \
                    MMA_F16(ACC[mt][nt], ah[mt], bh[nt][0], bh[nt][1]);       \
        }                                                                     \
        if (ck + 3 < nk) {                                                    \
            const uint32_t bufb2 = sb + (uint32_t)((ck + 3) & 3) * 16384;     \
            _Pragma("unroll")                                                 \
            for (int s = 0; s < 2; s++) {                                     \
                const int seg = cseg0 + s;                                    \
                const uint32_t so = bufb2 + soffA + (uint32_t)seg * 128;      \
                const size_t  go = (size_t)crow * K + (ck + 3) * 32 + seg * 8;\
                CP16(so,        Ab + go);                                     \
                CP16(so + 8192, Wb + go);                                     \
            }                                                                 \
        }                                                                     \
        CP_COMMIT();                                                          \
    }

// ============ tensor-core GEMM: C = relu?(A @ W^T + b) ======================
__global__ __launch_bounds__(256, 2) void gemm_tc(
    const fp16* __restrict__ A, const fp16* __restrict__ W,
    const float* __restrict__ bias,
    float* __restrict__ Cf, fp16* __restrict__ Ch,
    int K, int N, int relu)
{
    extern __shared__ unsigned char smem[];
    const uint32_t sb = smem_u32(smem);
    const int tid    = threadIdx.x;
    const int lane   = tid & 31;
    const int w      = tid >> 5;
    const int warp_m = w >> 2;
    const int warp_n = w & 3;
    const int row0   = blockIdx.y * 128;
    const int col0   = blockIdx.x * 128;

    float* sbias = (float*)(smem + 65536);
    if (tid < 128) sbias[tid] = bias[col0 + tid];

    const fp16* Ab = A + (size_t)row0 * K;
    const fp16* Wb = W + (size_t)col0 * K;

    float acc[4][4][4];
    #pragma unroll
    for (int i = 0; i < 4; i++)
        #pragma unroll
        for (int j = 0; j < 4; j++)
            #pragma unroll
            for (int e = 0; e < 4; e++) acc[i][j][e] = 0.0f;

    GEMM_MAINLOOP(acc)

    // ---- epilogue: bias + relu, fp32 or fp16 stores ----
    const int q  = lane >> 2;
    const int tq = lane & 3;
    #pragma unroll
    for (int mt = 0; mt < 4; mt++) {
        const int r0g = row0 + warp_m * 64 + mt * 16 + q;
        #pragma unroll
        for (int nt = 0; nt < 4; nt++) {
            const int cl = warp_n * 32 + nt * 8 + tq * 2;
            const float bx = sbias[cl], by = sbias[cl + 1];
            float v0 = acc[mt][nt][0] + bx, v1 = acc[mt][nt][1] + by;
            float v2 = acc[mt][nt][2] + bx, v3 = acc[mt][nt][3] + by;
            if (relu) {
                v0 = fmaxf(v0, 0.0f); v1 = fmaxf(v1, 0.0f);
                v2 = fmaxf(v2, 0.0f); v3 = fmaxf(v3, 0.0f);
            }
            const size_t o0 = (size_t)r0g * N + col0 + cl;
            const size_t o1 = (size_t)(r0g + 8) * N + col0 + cl;
            if (Cf) {
                *(float2*)(Cf + o0) = make_float2(v0, v1);
                *(float2*)(Cf + o1) = make_float2(v2, v3);
            }
            if (Ch) {
                *(__half2*)(Ch + o0) = __floats2half2_rn(v0, v1);
                *(__half2*)(Ch + o1) = __floats2half2_rn(v2, v3);
            }
        }
    }
}

// ====== fused last layers: relu(t3 @ u4^T + b4) . w5 -> per-half partials ===
// grid dim3(2, BATCH/128). K=512, N=256. Writes g_d2[row*2 + blockIdx.x].
__global__ __launch_bounds__(256, 2) void gemm_dot(
    const fp16* __restrict__ A, const fp16* __restrict__ W,
    const float* __restrict__ bias, const float* __restrict__ w5)
{
    extern __shared__ unsigned char smem[];
    const uint32_t sb = smem_u32(smem);
    const int tid    = threadIdx.x;
    const int lane   = tid & 31;
    const int w      = tid >> 5;
    const int warp_m = w >> 2;
    const int warp_n = w & 3;
    const int row0   = blockIdx.y * 128;
    const int col0   = blockIdx.x * 128;
    const int K = 512;

    float* sbias = (float*)(smem + 65536);
    float* sw5   = (float*)(smem + 65536 + 512);
    float* spart = (float*)(smem + 65536 + 1024);    // [128][4]
    if (tid < 128) {
        sbias[tid] = bias[col0 + tid];
        sw5[tid]   = w5[col0 + tid];
    }

    const fp16* Ab = A + (size_t)row0 * K;
    const fp16* Wb = W + (size_t)col0 * K;

    float acc[4][4][4];
    #pragma unroll
    for (int i = 0; i < 4; i++)
        #pragma unroll
        for (int j = 0; j < 4; j++)
            #pragma unroll
            for (int e = 0; e < 4; e++) acc[i][j][e] = 0.0f;

    GEMM_MAINLOOP(acc)

    // ---- epilogue: bias + relu + dot with w5, reduce to per-row partials ----
    const int q  = lane >> 2;
    const int tq = lane & 3;
    #pragma unroll
    for (int mt = 0; mt < 4; mt++) {
        float plo = 0.0f, phi = 0.0f;
        #pragma unroll
        for (int nt = 0; nt < 4; nt++) {
            const int cl = warp_n * 32 + nt * 8 + tq * 2;
            const float bx = sbias[cl], by = sbias[cl + 1];
            const float wx = sw5[cl],   wy = sw5[cl + 1];
            plo += fmaxf(acc[mt][nt][0] + bx, 0.0f) * wx
                 + fmaxf(acc[mt][nt][1] + by, 0.0f) * wy;
            phi += fmaxf(acc[mt][nt][2] + bx, 0.0f) * wx
                 + fmaxf(acc[mt][nt][3] + by, 0.0f) * wy;
        }
        // reduce across the 4 tq lanes (same rows)
        #pragma unroll
        for (int o = 1; o < 4; o <<= 1) {
            plo += __shfl_xor_sync(0xffffffffu, plo, o);
            phi += __shfl_xor_sync(0xffffffffu, phi, o);
        }
        if (tq == 0) {
            const int rl = warp_m * 64 + mt * 16 + q;
            spart[rl * 4 + warp_n]       = plo;
            spart[(rl + 8) * 4 + warp_n] = phi;
        }
    }
    __syncthreads();
    if (tid < 128) {
        const float s = spart[tid * 4] + spart[tid * 4 + 1]
                      + spart[tid * 4 + 2] + spart[tid * 4 + 3];
        g_d2[(size_t)(row0 + tid) * 2 + blockIdx.x] = s;
    }
}

// ---------------- final: combine partials + sigmoid -------------------------
__global__ __launch_bounds__(256) void sigmoid_kernel(
    const float* __restrict__ b5, float* __restrict__ out)
{
    const int b = blockIdx.x * 256 + threadIdx.x;
    const float s = g_d2[b * 2] + g_d2[b * 2 + 1] + b5[0];
    out[b] = 1.0f / (1.0f + expf(-s));
}

// -------- merged prep (fp32->fp16 weights) + bottom layer 1 ----------------
#define N_W2 (256 * 512)
#define N_W3 (128 * 256)
#define N_U1 (1024 * XDIM)
#define N_U2 (1024 * 1024)
#define N_U3 (512 * 1024)
#define N_U4 (256 * 512)
#define N_PREP (N_W2 + N_W3 + N_U1 + N_U2 + N_U3 + N_U4)
#define PREP_BLOCKS ((N_PREP + 255) / 256)

__global__ __launch_bounds__(256) void prep_bottom1_kernel(
    const float* __restrict__ bw2, const float* __restrict__ bw3,
    const float* __restrict__ tw1, const float* __restrict__ tw2,
    const float* __restrict__ tw3, const float* __restrict__ tw4,
    const float* __restrict__ X,   const float* __restrict__ W1,
    const float* __restrict__ b1)
{
    if (blockIdx.x < PREP_BLOCKS) {
        int i = blockIdx.x * 256 + threadIdx.x;
        if (i >= N_PREP) return;
        if (i < N_W2) { g_w2[i] = __float2half(bw2[i]); return; }
        i -= N_W2;
        if (i < N_W3) { g_w3[i] = __float2half(bw3[i]); return; }
        i -= N_W3;
        if (i < N_U1) { g_u1[i] = __float2half(tw1[i]); return; }
        i -= N_U1;
        if (i < N_U2) { g_u2[i] = __float2half(tw2[i]); return; }
        i -= N_U2;
        if (i < N_U3) { g_u3[i] = __float2half(tw3[i]); return; }
        i -= N_U3;
        g_u4[i] = __float2half(tw4[i]);
        return;
    }

    // bottom layer 1: [B,13] -> [B,512] fp16, relu
    __shared__ float ws[512 * 13];
    __shared__ float bs[512];
    __shared__ float xs[32 * 13];
    const int tid  = threadIdx.x;
    const int row0 = (blockIdx.x - PREP_BLOCKS) * 32;

    for (int i = tid; i < 512 * 13; i += 256) ws[i] = W1[i];
    for (int i = tid; i < 512;      i += 256) bs[i] = b1[i];
    for (int i = tid; i < 32 * 13;  i += 256) xs[i] = X[row0 * 13 + i];
    __syncthreads();

    for (int o = tid; o < 32 * 512; o += 256) {
        const int col = o & 511;
        const int row = o >> 9;
        float acc = bs[col];
        #pragma unroll
        for (int k = 0; k < 13; k++)
            acc = fmaf(xs[row * 13 + k], ws[col * 13 + k], acc);
        g_h1[(size_t)(row0 + row) * 512 + col] = __float2half(fmaxf(acc, 0.0f));
    }
}

// ---------------- gather + pairwise interactions (HMMA Gram) ---------------
__global__ __launch_bounds__(128) void interact_kernel(
    const int* __restrict__ cat, const float* __restrict__ emb)
{
    __shared__ __align__(16) unsigned char ism[4 * 8192];
    const int warp = threadIdx.x >> 5;
    const int lane = threadIdx.x & 31;
    const int b    = blockIdx.x * 4 + warp;
    unsigned char* F = ism + warp * 8192;
    const uint32_t fb = smem_u32(F);

    int idxs[NCAT];
    #pragma unroll
    for (int t = 0; t < NCAT; t++) idxs[t] = cat[t * BATCH + b];

    const int c0   = lane * 4;
    const int matc = c0 >> 3;
    const int innc = (c0 & 7) * 2;

    uint2 bv = ((const uint2*)(g_bt + (size_t)b * EMB))[lane];
    {
        const int mat = matc;
        *(uint2*)(F + mat * 128 + (innc ^ ((mat & 7) << 4))) = bv;
    }
    #pragma unroll
    for (int t = 0; t < NCAT; t++) {
        const int r = t + 1;
        float4 e = ((const float4*)(emb + ((size_t)t * 100000 + idxs[t]) * EMB))[lane];
        uint2 p;
        *(__half2*)&p.x = __floats2half2_rn(e.x, e.y);
        *(__half2*)&p.y = __floats2half2_rn(e.z, e.w);
        const int mat = ((r >> 3) << 4) + matc;
        *(uint2*)(F + mat * 128 + ((((r & 7) << 4) + innc) ^ ((mat & 7) << 4))) = p;
    }
    #pragma unroll
    for (int r = 27; r < 32; r++) {
        const int mat = ((r >> 3) << 4) + matc;
        *(uint2*)(F + mat * 128 + ((((r & 7) << 4) + innc) ^ ((mat & 7) << 4))) =
            make_uint2(0u, 0u);
    }
    __syncwarp();

    fp16* xrow = g_x + (size_t)b * XDIM;
    ((uint2*)xrow)[lane] = bv;
    if (lane == 0) xrow[479] = __float2half(0.0f);

    const int g2 = lane >> 3;
    const int lr = lane & 7;

    float acc[2][4][4];
    #pragma unroll
    for (int i = 0; i < 2; i++)
        #pragma unroll
        for (int j = 0; j < 4; j++)
            #pragma unroll
            for (int e = 0; e < 4; e++) acc[i][j][e] = 0.0f;

    #pragma unroll
    for (int k = 0; k < 8; k++) {
        uint32_t a[2][4], bb[4][2];
        #pragma unroll
        for (int mt = 0; mt < 2; mt++) {
            const int mA = ((mt * 2 + (g2 & 1)) << 4) + (k * 2 + (g2 >> 1));
            const uint32_t ad = fb + (uint32_t)(mA * 128)
                              + (uint32_t)((lr * 16) ^ ((mA & 7) << 4));
            LDSM4(a[mt][0], a[mt][1], a[mt][2], a[mt][3], ad);
        }
        #pragma unroll
        for (int np = 0; np < 2; np++) {
            const int mB = ((np * 2 + (g2 >> 1)) << 4) + (k * 2 + (g2 & 1));
            const uint32_t bd = fb + (uint32_t)(mB * 128)
                              + (uint32_t)((lr * 16) ^ ((mB & 7) << 4));
            uint32_t r0, r1, r2, r3;
            LDSM4(r0, r1, r2, r3, bd);
            bb[np*2][0] = r0;   bb[np*2][1] = r1;
            bb[np*2+1][0] = r2; bb[np*2+1][1] = r3;
        }
        #pragma unroll
        for (int mt = 0; mt < 2; mt++)
            #pragma unroll
            for (int nt = 0; nt < 4; nt++)
                MMA_F16(acc[mt][nt], a[mt], bb[nt][0], bb[nt][1]);
    }

    const int q  = lane >> 2;
    const int tq = lane & 3;
    #pragma unroll
    for (int mt = 0; mt < 2; mt++) {
        #pragma unroll
        for (int nt = 0; nt < 4; nt++) {
            const int r1 = mt * 16 + q;
            const int r2 = r1 + 8;
            const int cA = nt * 8 + tq * 2;
            const int cB = cA + 1;
            if (r1 < 27) {
                if (cA < r1) xrow[EMB + r1 * (r1 - 1) / 2 + cA] = __float2half(acc[mt][nt][0]);
                if (cB < r1) xrow[EMB + r1 * (r1 - 1) / 2 + cB] = __float2half(acc[mt][nt][1]);
            }
            if (r2 < 27) {
                if (cA < r2) xrow[EMB + r2 * (r2 - 1) / 2 + cA] = __float2half(acc[mt][nt][2]);
                if (cB < r2) xrow[EMB + r2 * (r2 - 1) / 2 + cB] = __float2half(acc[mt][nt][3]);
            }
        }
    }
}

// ---------------- launcher --------------------------------------------------
template <typename T>
static T* sym_addr(const void* symbol)
{
    void* p = nullptr;
    cudaGetSymbolAddress(&p, symbol);
    return (T*)p;
}

extern "C" void kernel_launch(void* const* d_in, const int* in_sizes, int n_in,
                              void* d_out, int out_size)
{
    const float* Xnum = (const float*)d_in[0];
    const int*   cat  = (const int*)  d_in[1];
    const float* emb  = (const float*)d_in[2];
    const float* bw1  = (const float*)d_in[3];
    const float* bb1  = (const float*)d_in[4];
    const float* bw2  = (const float*)d_in[5];
    const float* bb2  = (const float*)d_in[6];
    const float* bw3  = (const float*)d_in[7];
    const float* bb3  = (const float*)d_in[8];
    const float* tw1  = (const float*)d_in[9];
    const float* tb1  = (const float*)d_in[10];
    const float* tw2  = (const float*)d_in[11];
    const float* tb2  = (const float*)d_in[12];
    const float* tw3  = (const float*)d_in[13];
    const float* tb3  = (const float*)d_in[14];
    const float* tw4  = (const float*)d_in[15];
    const float* tb4  = (const float*)d_in[16];
    const float* tw5  = (const float*)d_in[17];
    const float* tb5  = (const float*)d_in[18];
    float* out = (float*)d_out;

    fp16* h1 = sym_addr<fp16>(g_h1);
    fp16* h2 = sym_addr<fp16>(g_h2);
    fp16* bt = sym_addr<fp16>(g_bt);
    fp16* x  = sym_addr<fp16>(g_x);
    fp16* t1 = sym_addr<fp16>(g_t1);
    fp16* t2 = sym_addr<fp16>(g_t2);
    fp16* t3 = sym_addr<fp16>(g_t3);
    fp16* w2 = sym_addr<fp16>(g_w2);
    fp16* w3 = sym_addr<fp16>(g_w3);
    fp16* u1 = sym_addr<fp16>(g_u1);
    fp16* u2 = sym_addr<fp16>(g_u2);
    fp16* u3 = sym_addr<fp16>(g_u3);
    fp16* u4 = sym_addr<fp16>(g_u4);

    cudaFuncSetAttribute(gemm_tc,
                         cudaFuncAttributeMaxDynamicSharedMemorySize, GEMM_SMEM);
    cudaFuncSetAttribute(gemm_dot,
                         cudaFuncAttributeMaxDynamicSharedMemorySize, DOT_SMEM);

    // merged weight prep + bottom layer 1 (1 launch)
    prep_bottom1_kernel<<<PREP_BLOCKS + BATCH / 32, 256>>>(
        bw2, bw3, tw1, tw2, tw3, tw4, Xnum, bw1, bb1);

    // bottom MLP
    gemm_tc<<<dim3(2, BATCH / 128), 256, GEMM_SMEM>>>(
        h1, w2, bb2, nullptr, h2, 512, 256, 1);
    gemm_tc<<<dim3(1, BATCH / 128), 256, GEMM_SMEM>>>(
        h2, w3, bb3, nullptr, bt, 256, 128, 1);

    // gather + interactions -> x [B, 480] fp16
    interact_kernel<<<BATCH / 4, 128>>>(cat, emb);

    // top MLP
    gemm_tc<<<dim3(8, BATCH / 128), 256, GEMM_SMEM>>>(
        x,  u1, tb1, nullptr, t1, XDIM, 1024, 1);
    gemm_tc<<<dim3(8, BATCH / 128), 256, GEMM_SMEM>>>(
        t1, u2, tb2, nullptr, t2, 1024, 1024, 1);
    gemm_tc<<<dim3(4, BATCH / 128), 256, GEMM_SMEM>>>(
        t2, u3, tb3, nullptr, t3, 1024, 512, 1);

    // fused: relu(t3 @ u4^T + b4) . w5 -> partials; then sigmoid
    gemm_dot<<<dim3(2, BATCH / 128), 256, DOT_SMEM>>>(t3, u4, tb4, tw5);
    sigmoid_kernel<<<BATCH / 256, 256>>>(tb5, out);
}